// round 1
// baseline (speedup 1.0000x reference)
#include <cuda_runtime.h>
#include <cuda_bf16.h>
#include <math.h>

// Problem constants (dataset-fixed): C=128, K=32, N=200000, B=16.
#define C_DIM 128
#define K_DIM 32
#define N_MAX 200704

// ---------------- scratch (no allocations allowed) ----------------
__device__ float g_L[(size_t)N_MAX * K_DIM];  // logits [N,32]
__device__ float g_u[N_MAX];                  // row potentials
__device__ float g_v[K_DIM];                  // col potentials
__device__ float g_t[K_DIM];                  // col-sum accumulators

// ---------------- init ----------------
__global__ void k_init() {
    int k = threadIdx.x;
    if (k < K_DIM) { g_v[k] = 0.f; g_t[k] = 0.f; }
}

// ---------------- fused MLP -> logits ----------------
// One block computes 128 rows of logits. smem: xT[128][128] (k-major),
// W1[128][128], W2[128][32], b1[128]. h tile overwrites xT for GEMM2.
#define BM 128
#define SMEM_LOGITS ((128*128 + 128*128 + 128*32 + 128) * 4)

__global__ void __launch_bounds__(256, 1)
k_logits(const float* __restrict__ x, const float* __restrict__ W1,
         const float* __restrict__ b1, const float* __restrict__ W2,
         const float* __restrict__ b2, const float* __restrict__ scaling,
         int N)
{
    extern __shared__ float sm[];
    float* xsT = sm;                   // [k][i] 128x128
    float* W1s = sm + 128 * BM;        // [k][j] 128x128
    float* W2s = W1s + 128 * 128;      // [k][j] 128x32
    float* b1s = W2s + 128 * 32;       // [128]

    const int tid  = threadIdx.x;
    const int row0 = blockIdx.x * BM;

    // load W1 (row-major [k][j]) -> same layout in smem, coalesced float4
    for (int idx = tid; idx < 128 * 128 / 4; idx += 256)
        ((float4*)W1s)[idx] = ((const float4*)W1)[idx];
    for (int idx = tid; idx < 128 * 32 / 4; idx += 256)
        ((float4*)W2s)[idx] = ((const float4*)W2)[idx];
    if (tid < 128) b1s[tid] = b1[tid];

    // load x tile transposed: xsT[k][i] = x[row0+i][k]
    for (int f = tid; f < BM * 32; f += 256) {
        int i = f >> 5, kq = f & 31;
        int r = row0 + i;
        float4 v = (r < N) ? ((const float4*)x)[(size_t)r * 32 + kq]
                           : make_float4(0.f, 0.f, 0.f, 0.f);
        xsT[(kq * 4 + 0) * BM + i] = v.x;
        xsT[(kq * 4 + 1) * BM + i] = v.y;
        xsT[(kq * 4 + 2) * BM + i] = v.z;
        xsT[(kq * 4 + 3) * BM + i] = v.w;
    }
    __syncthreads();

    // ---- GEMM1: h = x @ W1, 8x8 per thread ----
    const int tx = tid & 15, ty = tid >> 4;
    float acc[8][8];
#pragma unroll
    for (int r = 0; r < 8; r++)
#pragma unroll
        for (int c = 0; c < 8; c++) acc[r][c] = 0.f;

    const float* aPtr = &xsT[ty * 8];
    const float* bPtr = &W1s[tx * 8];
#pragma unroll 2
    for (int kk = 0; kk < 128; kk++) {
        float4 a0 = *(const float4*)(aPtr + kk * BM);
        float4 a1 = *(const float4*)(aPtr + kk * BM + 4);
        float4 w0 = *(const float4*)(bPtr + kk * 128);
        float4 w1 = *(const float4*)(bPtr + kk * 128 + 4);
        float av[8] = {a0.x, a0.y, a0.z, a0.w, a1.x, a1.y, a1.z, a1.w};
        float wv[8] = {w0.x, w0.y, w0.z, w0.w, w1.x, w1.y, w1.z, w1.w};
#pragma unroll
        for (int r = 0; r < 8; r++)
#pragma unroll
            for (int c = 0; c < 8; c++)
                acc[r][c] = fmaf(av[r], wv[c], acc[r][c]);
    }
    __syncthreads();  // all GEMM1 reads of xsT done

    // bias + relu, write h transposed into xsT: xsT[j][i] = h[i][j]
#pragma unroll
    for (int c = 0; c < 8; c++) {
        float bb = b1s[tx * 8 + c];
#pragma unroll
        for (int r = 0; r < 8; r++)
            xsT[(tx * 8 + c) * BM + (ty * 8 + r)] = fmaxf(acc[r][c] + bb, 0.f);
    }
    __syncthreads();

    // ---- GEMM2: logits = h @ W2, 2 rows x 8 cols per thread ----
    const int tx2 = tid & 3, ty2 = tid >> 2;
    float acc2[2][8];
#pragma unroll
    for (int r = 0; r < 2; r++)
#pragma unroll
        for (int c = 0; c < 8; c++) acc2[r][c] = 0.f;

#pragma unroll 4
    for (int kk = 0; kk < 128; kk++) {
        float a0 = xsT[kk * BM + ty2 * 2];
        float a1 = xsT[kk * BM + ty2 * 2 + 1];
        float4 w0 = *(const float4*)&W2s[kk * 32 + tx2 * 8];
        float4 w1 = *(const float4*)&W2s[kk * 32 + tx2 * 8 + 4];
        float wv[8] = {w0.x, w0.y, w0.z, w0.w, w1.x, w1.y, w1.z, w1.w};
#pragma unroll
        for (int c = 0; c < 8; c++) {
            acc2[0][c] = fmaf(a0, wv[c], acc2[0][c]);
            acc2[1][c] = fmaf(a1, wv[c], acc2[1][c]);
        }
    }

    float sc = __ldg(scaling);
    float bb2[8];
#pragma unroll
    for (int c = 0; c < 8; c++) bb2[c] = b2[tx2 * 8 + c];

#pragma unroll
    for (int r = 0; r < 2; r++) {
        int row = row0 + ty2 * 2 + r;
        if (row < N) {
            float4 o0 = make_float4((acc2[r][0] + bb2[0]) * sc, (acc2[r][1] + bb2[1]) * sc,
                                    (acc2[r][2] + bb2[2]) * sc, (acc2[r][3] + bb2[3]) * sc);
            float4 o1 = make_float4((acc2[r][4] + bb2[4]) * sc, (acc2[r][5] + bb2[5]) * sc,
                                    (acc2[r][6] + bb2[6]) * sc, (acc2[r][7] + bb2[7]) * sc);
            float4* dst = (float4*)&g_L[(size_t)row * 32 + tx2 * 8];
            dst[0] = o0;
            dst[1] = o1;
        }
    }
}

// ---------------- Sinkhorn row pass ----------------
// u[n] = LSE_k(L[n,k] - v[k]); accumulate t_k += exp(L - v - u) (row softmax probs)
__global__ void __launch_bounds__(256)
k_row(int N)
{
    __shared__ float vsh[K_DIM];
    __shared__ float csum[K_DIM];
    __shared__ float es[256 * 33];

    const int tid = threadIdx.x;
    if (tid < K_DIM) { vsh[tid] = g_v[tid]; csum[tid] = 0.f; }
    __syncthreads();

    const int n = blockIdx.x * 256 + tid;
    if (n < N) {
        const float4* Lr = (const float4*)&g_L[(size_t)n * 32];
        float d[32];
        float m = -1e30f;
#pragma unroll
        for (int q = 0; q < 8; q++) {
            float4 lv = Lr[q];
            d[4 * q + 0] = lv.x - vsh[4 * q + 0];
            d[4 * q + 1] = lv.y - vsh[4 * q + 1];
            d[4 * q + 2] = lv.z - vsh[4 * q + 2];
            d[4 * q + 3] = lv.w - vsh[4 * q + 3];
            m = fmaxf(m, fmaxf(fmaxf(d[4 * q], d[4 * q + 1]), fmaxf(d[4 * q + 2], d[4 * q + 3])));
        }
        float ssum = 0.f;
#pragma unroll
        for (int j = 0; j < 32; j++) {
            float ej = __expf(d[j] - m);
            es[tid * 33 + j] = ej;
            ssum += ej;
        }
        g_u[n] = m + __logf(ssum);
        float inv = 1.0f / ssum;
        const int lane = tid & 31;
#pragma unroll
        for (int it = 0; it < 32; it++) {
            int k = (it + lane) & 31;  // skew: lanes hit distinct banks
            atomicAdd(&csum[k], es[tid * 33 + k] * inv);
        }
    }
    __syncthreads();
    if (tid < K_DIM) atomicAdd(&g_t[tid], csum[tid]);
}

// ---------------- Sinkhorn col update ----------------
// v[k] += log(t_k) - log(N/K + 1e-9);  (exact log-domain col LSE since t_k was
// computed with shift v_old+u)
__global__ void k_col(float lognk)
{
    int k = threadIdx.x;
    if (k < K_DIM) {
        g_v[k] += __logf(g_t[k]) - lognk;
        g_t[k] = 0.f;
    }
}

// ---------------- pooled scatter: out[b,k,c] += exp(L-u-v)*x[n,c] ----------------
// batch is sorted -> contiguous segments; register 4x4 tile per thread, flush on
// segment change with atomicAdd.
__global__ void __launch_bounds__(256)
k_pool(const float* __restrict__ x, const int* __restrict__ batch,
       float* __restrict__ out, int N, int rows_per_block)
{
    __shared__ float xs[8][128];
    __shared__ float ss[8][32];
    __shared__ int   bs[8];
    __shared__ float vsh[K_DIM];

    const int tid = threadIdx.x;
    if (tid < K_DIM) vsh[tid] = g_v[tid];

    const int start = blockIdx.x * rows_per_block;
    const int end   = min(start + rows_per_block, N);
    const int kg = tid >> 5;  // 0..7 -> k base kg*4
    const int cg = tid & 31;  // c base cg*4

    float acc[4][4];
#pragma unroll
    for (int i = 0; i < 4; i++)
#pragma unroll
        for (int j = 0; j < 4; j++) acc[i][j] = 0.f;
    int cur_b = -1;

    for (int s0 = start; s0 < end; s0 += 8) {
        int nr = min(8, end - s0);
        __syncthreads();  // protect smem reuse
        for (int f = tid; f < nr * 32; f += 256) {
            int r = f >> 5, q = f & 31;
            ((float4*)xs[r])[q] = ((const float4*)x)[(size_t)(s0 + r) * 32 + q];
        }
        for (int f = tid; f < nr * 32; f += 256) {
            int r = f >> 5, k = f & 31;
            ss[r][k] = __expf(g_L[(size_t)(s0 + r) * 32 + k] - g_u[s0 + r] - vsh[k]);
        }
        if (tid < nr) bs[tid] = batch[s0 + tid];
        __syncthreads();

        for (int r = 0; r < nr; r++) {
            int bn = bs[r];
            if (bn != cur_b) {  // uniform across block
                if (cur_b >= 0) {
#pragma unroll
                    for (int i = 0; i < 4; i++)
#pragma unroll
                        for (int j = 0; j < 4; j++) {
                            atomicAdd(&out[((cur_b * 32 + kg * 4 + i) << 7) + cg * 4 + j],
                                      acc[i][j]);
                            acc[i][j] = 0.f;
                        }
                }
                cur_b = bn;
            }
            float4 sv = *(const float4*)&ss[r][kg * 4];
            float4 xv = *(const float4*)&xs[r][cg * 4];
            float svv[4] = {sv.x, sv.y, sv.z, sv.w};
            float xvv[4] = {xv.x, xv.y, xv.z, xv.w};
#pragma unroll
            for (int i = 0; i < 4; i++)
#pragma unroll
                for (int j = 0; j < 4; j++)
                    acc[i][j] = fmaf(svv[i], xvv[j], acc[i][j]);
        }
    }
    if (cur_b >= 0) {
#pragma unroll
        for (int i = 0; i < 4; i++)
#pragma unroll
            for (int j = 0; j < 4; j++)
                atomicAdd(&out[((cur_b * 32 + kg * 4 + i) << 7) + cg * 4 + j], acc[i][j]);
    }
}

// ---------------- launch ----------------
extern "C" void kernel_launch(void* const* d_in, const int* in_sizes, int n_in,
                              void* d_out, int out_size)
{
    const float* x       = (const float*)d_in[0];
    const int*   batch   = (const int*)d_in[1];
    const float* W1      = (const float*)d_in[2];
    const float* b1      = (const float*)d_in[3];
    const float* W2      = (const float*)d_in[4];
    const float* b2      = (const float*)d_in[5];
    const float* scaling = (const float*)d_in[6];

    const int N = in_sizes[0] / C_DIM;

    cudaFuncSetAttribute(k_logits, cudaFuncAttributeMaxDynamicSharedMemorySize, SMEM_LOGITS);

    k_init<<<1, 32>>>();
    k_logits<<<(N + BM - 1) / BM, 256, SMEM_LOGITS>>>(x, W1, b1, W2, b2, scaling, N);

    const float lognk = logf((float)N / (float)K_DIM + 1e-9f);
    for (int it = 0; it < 20; it++) {
        k_row<<<(N + 255) / 256, 256>>>(N);
        k_col<<<1, 32>>>(lognk);
    }

    cudaMemsetAsync(d_out, 0, (size_t)out_size * sizeof(float));
    const int G = 592;
    const int rpb = (N + G - 1) / G;
    k_pool<<<G, 256>>>(x, batch, (float*)d_out, N, rpb);
}

// round 2
// speedup vs baseline: 1.5202x; 1.5202x over previous
#include <cuda_runtime.h>
#include <cuda_bf16.h>
#include <math.h>

// Problem constants (dataset-fixed): C=128, K=32, N=200000, B=16.
#define C_DIM 128
#define K_DIM 32
#define N_MAX 200704
#define ITERS 20

// ---------------- scratch (no allocations allowed) ----------------
__device__ float g_L[(size_t)N_MAX * K_DIM];       // logits [N,32]
__device__ float g_t[ITERS][K_DIM];                // per-iter column sums
__device__ unsigned int g_arrive = 0;              // grid barrier
__device__ unsigned int g_gen = 0;

// ---------------- init ----------------
__global__ void k_init() {
    int i = blockIdx.x * blockDim.x + threadIdx.x;
    if (i < ITERS * K_DIM) ((float*)g_t)[i] = 0.f;
}

// ---------------- fused MLP -> logits (fp32 SIMT GEMM, unchanged) ----------------
#define BM 128
#define SMEM_LOGITS ((128*128 + 128*128 + 128*32 + 128) * 4)

__global__ void __launch_bounds__(256, 1)
k_logits(const float* __restrict__ x, const float* __restrict__ W1,
         const float* __restrict__ b1, const float* __restrict__ W2,
         const float* __restrict__ b2, const float* __restrict__ scaling,
         int N)
{
    extern __shared__ float sm[];
    float* xsT = sm;                   // [k][i] 128x128
    float* W1s = sm + 128 * BM;        // [k][j] 128x128
    float* W2s = W1s + 128 * 128;      // [k][j] 128x32
    float* b1s = W2s + 128 * 32;       // [128]

    const int tid  = threadIdx.x;
    const int row0 = blockIdx.x * BM;

    for (int idx = tid; idx < 128 * 128 / 4; idx += 256)
        ((float4*)W1s)[idx] = ((const float4*)W1)[idx];
    for (int idx = tid; idx < 128 * 32 / 4; idx += 256)
        ((float4*)W2s)[idx] = ((const float4*)W2)[idx];
    if (tid < 128) b1s[tid] = b1[tid];

    for (int f = tid; f < BM * 32; f += 256) {
        int i = f >> 5, kq = f & 31;
        int r = row0 + i;
        float4 v = (r < N) ? ((const float4*)x)[(size_t)r * 32 + kq]
                           : make_float4(0.f, 0.f, 0.f, 0.f);
        xsT[(kq * 4 + 0) * BM + i] = v.x;
        xsT[(kq * 4 + 1) * BM + i] = v.y;
        xsT[(kq * 4 + 2) * BM + i] = v.z;
        xsT[(kq * 4 + 3) * BM + i] = v.w;
    }
    __syncthreads();

    // ---- GEMM1: h = x @ W1, 8x8 per thread ----
    const int tx = tid & 15, ty = tid >> 4;
    float acc[8][8];
#pragma unroll
    for (int r = 0; r < 8; r++)
#pragma unroll
        for (int c = 0; c < 8; c++) acc[r][c] = 0.f;

    const float* aPtr = &xsT[ty * 8];
    const float* bPtr = &W1s[tx * 8];
#pragma unroll 2
    for (int kk = 0; kk < 128; kk++) {
        float4 a0 = *(const float4*)(aPtr + kk * BM);
        float4 a1 = *(const float4*)(aPtr + kk * BM + 4);
        float4 w0 = *(const float4*)(bPtr + kk * 128);
        float4 w1 = *(const float4*)(bPtr + kk * 128 + 4);
        float av[8] = {a0.x, a0.y, a0.z, a0.w, a1.x, a1.y, a1.z, a1.w};
        float wv[8] = {w0.x, w0.y, w0.z, w0.w, w1.x, w1.y, w1.z, w1.w};
#pragma unroll
        for (int r = 0; r < 8; r++)
#pragma unroll
            for (int c = 0; c < 8; c++)
                acc[r][c] = fmaf(av[r], wv[c], acc[r][c]);
    }
    __syncthreads();

    // bias + relu, write h transposed into xsT: xsT[j][i] = h[i][j]
#pragma unroll
    for (int c = 0; c < 8; c++) {
        float bb = b1s[tx * 8 + c];
#pragma unroll
        for (int r = 0; r < 8; r++)
            xsT[(tx * 8 + c) * BM + (ty * 8 + r)] = fmaxf(acc[r][c] + bb, 0.f);
    }
    __syncthreads();

    // ---- GEMM2: logits = h @ W2 ----
    const int tx2 = tid & 3, ty2 = tid >> 2;
    float acc2[2][8];
#pragma unroll
    for (int r = 0; r < 2; r++)
#pragma unroll
        for (int c = 0; c < 8; c++) acc2[r][c] = 0.f;

#pragma unroll 4
    for (int kk = 0; kk < 128; kk++) {
        float a0 = xsT[kk * BM + ty2 * 2];
        float a1 = xsT[kk * BM + ty2 * 2 + 1];
        float4 w0 = *(const float4*)&W2s[kk * 32 + tx2 * 8];
        float4 w1 = *(const float4*)&W2s[kk * 32 + tx2 * 8 + 4];
        float wv[8] = {w0.x, w0.y, w0.z, w0.w, w1.x, w1.y, w1.z, w1.w};
#pragma unroll
        for (int c = 0; c < 8; c++) {
            acc2[0][c] = fmaf(a0, wv[c], acc2[0][c]);
            acc2[1][c] = fmaf(a1, wv[c], acc2[1][c]);
        }
    }

    float sc = __ldg(scaling);
    float bb2[8];
#pragma unroll
    for (int c = 0; c < 8; c++) bb2[c] = b2[tx2 * 8 + c];

#pragma unroll
    for (int r = 0; r < 2; r++) {
        int row = row0 + ty2 * 2 + r;
        if (row < N) {
            float4 o0 = make_float4((acc2[r][0] + bb2[0]) * sc, (acc2[r][1] + bb2[1]) * sc,
                                    (acc2[r][2] + bb2[2]) * sc, (acc2[r][3] + bb2[3]) * sc);
            float4 o1 = make_float4((acc2[r][4] + bb2[4]) * sc, (acc2[r][5] + bb2[5]) * sc,
                                    (acc2[r][6] + bb2[6]) * sc, (acc2[r][7] + bb2[7]) * sc);
            float4* dst = (float4*)&g_L[(size_t)row * 32 + tx2 * 8];
            dst[0] = o0;
            dst[1] = o1;
        }
    }
}

// ---------------- software grid barrier (all blocks resident: 1 block/SM) ----------------
__device__ __forceinline__ void grid_barrier(unsigned int nb)
{
    __syncthreads();
    if (threadIdx.x == 0) {
        __threadfence();
        unsigned int gen = *(volatile unsigned int*)&g_gen;
        if (atomicAdd(&g_arrive, 1u) == nb - 1u) {
            g_arrive = 0u;
            __threadfence();
            *(volatile unsigned int*)&g_gen = gen + 1u;
        } else {
            while (*(volatile unsigned int*)&g_gen == gen) { __nanosleep(64); }
        }
        __threadfence();
    }
    __syncthreads();
}

// ---------------- persistent fused Sinkhorn + pooling ----------------
// Linear-domain Sinkhorn on E = exp(L - rowmax), held entirely in smem.
//   iter: r[n] = 1/sum_k(E*c);  t_k = sum_n(E*r) (global atomics);  c[k] = (N/K)/t_k
// Exactly equivalent to the reference log-domain recursion (rowmax folds into r).
// Then out[b,k,c] += (E*r*c) * x[n,c] with register 4x4 tiles + segment flush.
__global__ void __launch_bounds__(256, 1)
k_sinkpool(const float* __restrict__ x, const int* __restrict__ batch,
           float* __restrict__ out, int N, int rpb, unsigned int nb, float NK)
{
    extern __shared__ float sm[];
    float* E   = sm;                        // [rpb][33] padded, conflict-free
    float* r   = E + (size_t)rpb * 33;      // [rpb]
    float* c   = r + rpb;                   // [32]
    float* red = c + 32;                    // [8][33]
    float* xs  = red + 8 * 33;              // [8][128]
    float* ss  = xs + 8 * 128;              // [8][32]
    int*   bs  = (int*)(ss + 8 * 32);       // [8]

    const int tid  = threadIdx.x;
    const int lane = tid & 31;
    const int wid  = tid >> 5;
    const int n0   = blockIdx.x * rpb;
    const int cnt  = max(0, min(rpb, N - n0));

    // ---- load logits chunk (coalesced) into padded smem ----
    for (int idx = tid * 4; idx < cnt * 32; idx += 256 * 4) {
        float4 v = *(const float4*)&g_L[(size_t)n0 * 32 + idx];
        int row = idx >> 5, k = idx & 31;
        float* dst = &E[row * 33 + k];
        dst[0] = v.x; dst[1] = v.y; dst[2] = v.z; dst[3] = v.w;
    }
    if (tid < 32) c[tid] = 1.f;
    __syncthreads();

    // ---- E = exp(L - rowmax), in place (one exp pass total) ----
    for (int row = tid; row < cnt; row += 256) {
        float* Er = &E[row * 33];
        float m = -1e30f;
#pragma unroll
        for (int k = 0; k < 32; k++) m = fmaxf(m, Er[k]);
#pragma unroll
        for (int k = 0; k < 32; k++) Er[k] = __expf(Er[k] - m);
    }
    __syncthreads();

    // ---- 20 Sinkhorn iterations, all in smem ----
    for (int it = 0; it < ITERS; it++) {
        float tl[32];
#pragma unroll
        for (int k = 0; k < 32; k++) tl[k] = 0.f;

        for (int row = tid; row < cnt; row += 256) {
            const float* Er = &E[row * 33];
            float s = 0.f;
#pragma unroll
            for (int k = 0; k < 32; k++) s = fmaf(Er[k], c[k], s);
            float rr = 1.0f / s;
            r[row] = rr;
#pragma unroll
            for (int k = 0; k < 32; k++) tl[k] = fmaf(Er[k], rr, tl[k]);
        }

        // warp-reduce 32 partials; lane l ends owning k=l
        float mine = 0.f;
#pragma unroll
        for (int k = 0; k < 32; k++) {
            float v = tl[k];
            v += __shfl_xor_sync(0xffffffffu, v, 16);
            v += __shfl_xor_sync(0xffffffffu, v, 8);
            v += __shfl_xor_sync(0xffffffffu, v, 4);
            v += __shfl_xor_sync(0xffffffffu, v, 2);
            v += __shfl_xor_sync(0xffffffffu, v, 1);
            if (lane == k) mine = v;
        }
        red[wid * 33 + lane] = mine;
        __syncthreads();
        if (tid < 32) {
            float s = 0.f;
#pragma unroll
            for (int w = 0; w < 8; w++) s += red[w * 33 + tid];
            atomicAdd(&g_t[it][tid], s);
        }

        grid_barrier(nb);

        if (tid < 32) c[tid] = NK / __ldcg(&g_t[it][tid]);
        __syncthreads();
    }

    // ---- pooling: out[b,k,c] += E*r*c * x  (batch sorted -> segment flush) ----
    const int kg = tid >> 5;   // k base = kg*4
    const int cg = tid & 31;   // c base = cg*4
    float acc[4][4];
#pragma unroll
    for (int i = 0; i < 4; i++)
#pragma unroll
        for (int j = 0; j < 4; j++) acc[i][j] = 0.f;
    int cur_b = -1;

    for (int s0 = 0; s0 < cnt; s0 += 8) {
        int nr = min(8, cnt - s0);
        __syncthreads();
        for (int f = tid; f < nr * 32; f += 256) {
            int rr = f >> 5, q = f & 31;
            ((float4*)(xs + rr * 128))[q] = ((const float4*)x)[(size_t)(n0 + s0 + rr) * 32 + q];
        }
        for (int f = tid; f < nr * 32; f += 256) {
            int rr = f >> 5, k = f & 31;
            ss[rr * 32 + k] = E[(s0 + rr) * 33 + k] * r[s0 + rr] * c[k];
        }
        if (tid < nr) bs[tid] = batch[n0 + s0 + tid];
        __syncthreads();

        for (int rr = 0; rr < nr; rr++) {
            int bn = bs[rr];
            if (bn != cur_b) {
                if (cur_b >= 0) {
#pragma unroll
                    for (int i = 0; i < 4; i++)
#pragma unroll
                        for (int j = 0; j < 4; j++) {
                            atomicAdd(&out[((cur_b * 32 + kg * 4 + i) << 7) + cg * 4 + j],
                                      acc[i][j]);
                            acc[i][j] = 0.f;
                        }
                }
                cur_b = bn;
            }
            float4 sv = *(const float4*)&ss[rr * 32 + kg * 4];
            float4 xv = *(const float4*)&xs[rr * 128 + cg * 4];
            float svv[4] = {sv.x, sv.y, sv.z, sv.w};
            float xvv[4] = {xv.x, xv.y, xv.z, xv.w};
#pragma unroll
            for (int i = 0; i < 4; i++)
#pragma unroll
                for (int j = 0; j < 4; j++)
                    acc[i][j] = fmaf(svv[i], xvv[j], acc[i][j]);
        }
    }
    if (cur_b >= 0) {
#pragma unroll
        for (int i = 0; i < 4; i++)
#pragma unroll
            for (int j = 0; j < 4; j++)
                atomicAdd(&out[((cur_b * 32 + kg * 4 + i) << 7) + cg * 4 + j], acc[i][j]);
    }
}

// ---------------- launch ----------------
extern "C" void kernel_launch(void* const* d_in, const int* in_sizes, int n_in,
                              void* d_out, int out_size)
{
    const float* x       = (const float*)d_in[0];
    const int*   batch   = (const int*)d_in[1];
    const float* W1      = (const float*)d_in[2];
    const float* b1      = (const float*)d_in[3];
    const float* W2      = (const float*)d_in[4];
    const float* b2      = (const float*)d_in[5];
    const float* scaling = (const float*)d_in[6];

    const int N = in_sizes[0] / C_DIM;

    // one persistent block per SM (1 block/SM forced by ~190KB smem)
    int dev = 0, nsm = 148;
    cudaGetDevice(&dev);
    cudaDeviceGetAttribute(&nsm, cudaDevAttrMultiProcessorCount, dev);
    unsigned int nb = (unsigned int)nsm;
    int rpb = (N + (int)nb - 1) / (int)nb;
    size_t smem2 = ((size_t)rpb * 34 + 32 + 8 * 33 + 8 * 128 + 8 * 32 + 16) * 4;

    cudaFuncSetAttribute(k_logits, cudaFuncAttributeMaxDynamicSharedMemorySize, SMEM_LOGITS);
    cudaFuncSetAttribute(k_sinkpool, cudaFuncAttributeMaxDynamicSharedMemorySize, (int)smem2);

    k_init<<<1, ITERS * K_DIM>>>();
    k_logits<<<(N + BM - 1) / BM, 256, SMEM_LOGITS>>>(x, W1, b1, W2, b2, scaling, N);

    cudaMemsetAsync(d_out, 0, (size_t)out_size * sizeof(float));

    const float NK = (float)N / (float)K_DIM + 1e-9f;
    k_sinkpool<<<nb, 256, smem2>>>(x, batch, (float*)d_out, N, rpb, nb, NK);
}

// round 4
// speedup vs baseline: 1.9078x; 1.2549x over previous
#include <cuda_runtime.h>
#include <cuda_bf16.h>
#include <mma.h>
#include <math.h>
#include <stdint.h>

using namespace nvcuda;

// Problem constants (dataset-fixed): C=128, K=32, N=200000, B=16.
#define C_DIM 128
#define K_DIM 32
#define N_MAX 200704
#define ITERS 20

// ---------------- scratch ----------------
__device__ float g_L[(size_t)N_MAX * K_DIM];       // logits [N,32]
__device__ float g_t[ITERS][K_DIM];                // per-iter column sums
__device__ unsigned int g_arrive = 0;
__device__ unsigned int g_gen = 0;

// split 4 consecutive floats into hi/lo bf16x2 pairs (uint2 = 4 bf16)
__device__ __forceinline__ void split4(float a, float b, float c, float d, uint2& hi, uint2& lo) {
    __nv_bfloat162 h0 = __floats2bfloat162_rn(a, b);
    __nv_bfloat162 h1 = __floats2bfloat162_rn(c, d);
    __nv_bfloat162 l0 = __floats2bfloat162_rn(a - __low2float(h0), b - __high2float(h0));
    __nv_bfloat162 l1 = __floats2bfloat162_rn(c - __low2float(h1), d - __high2float(h1));
    hi.x = *reinterpret_cast<uint32_t*>(&h0);
    hi.y = *reinterpret_cast<uint32_t*>(&h1);
    lo.x = *reinterpret_cast<uint32_t*>(&l0);
    lo.y = *reinterpret_cast<uint32_t*>(&l1);
}

// ================= wmma (HMMA bf16) fused MLP -> logits =================
// smem layout (bytes). A/H: [128][LDA] bf16 (hi,lo). W1T: col-major (k fast) [n=128][LDA];
// its region is reused for the fp32 D scratch after GEMM1. W2T: [n=32][LDA].
#define LDA   136   // bf16 leading dim (272 B rows)
#define LDD   132   // fp32 leading dim for D1 (128x128)
#define LDD2  36    // fp32 leading dim for D2 (128x32)

#define OF_AHI  0
#define OF_ALO  (OF_AHI + 128 * LDA * 2)            // 34816
#define OF_W1HI (OF_ALO + 128 * LDA * 2)            // 69632
#define OF_W1LO (OF_W1HI + 128 * LDA * 2)           // 104448
#define OF_DW   OF_W1HI                             // D1 fp32 [128][132] = 67584 (reuses W1)
#define OF_W2HI (OF_W1LO + 128 * LDA * 2)           // 139264
#define OF_W2LO (OF_W2HI + 32 * LDA * 2)            // 147968
#define OF_B1   (OF_W2LO + 32 * LDA * 2)            // 156672
#define OF_B2   (OF_B1 + 512)
#define SMEM_TC (OF_B2 + 128)

__global__ void __launch_bounds__(256, 1)
k_logits_tc(const float* __restrict__ x, const float* __restrict__ W1,
            const float* __restrict__ b1, const float* __restrict__ W2,
            const float* __restrict__ b2, const float* __restrict__ scaling, int N)
{
    extern __shared__ char sm[];
    __nv_bfloat16* Ahi  = (__nv_bfloat16*)(sm + OF_AHI);
    __nv_bfloat16* Alo  = (__nv_bfloat16*)(sm + OF_ALO);
    __nv_bfloat16* W1hi = (__nv_bfloat16*)(sm + OF_W1HI);
    __nv_bfloat16* W1lo = (__nv_bfloat16*)(sm + OF_W1LO);
    __nv_bfloat16* W2hi = (__nv_bfloat16*)(sm + OF_W2HI);
    __nv_bfloat16* W2lo = (__nv_bfloat16*)(sm + OF_W2LO);
    float* DW  = (float*)(sm + OF_DW);
    float* b1s = (float*)(sm + OF_B1);
    float* b2s = (float*)(sm + OF_B2);

    const int tid = threadIdx.x, wid = tid >> 5;
    const int row0 = blockIdx.x * 128;

    if (tid < 128) b1s[tid] = b1[tid];
    else if (tid < 160) b2s[tid - 128] = b2[tid - 128];

    // ---- W1^T split: W1T[n=j][k] = W1[k][j] (col-major B, k contiguous) ----
    for (int f = tid; f < 4096; f += 256) {
        int j = f & 127, k0 = (f >> 7) * 4;           // coalesced in j per k row
        float v0 = W1[(k0 + 0) * 128 + j];
        float v1 = W1[(k0 + 1) * 128 + j];
        float v2 = W1[(k0 + 2) * 128 + j];
        float v3 = W1[(k0 + 3) * 128 + j];
        uint2 hi, lo; split4(v0, v1, v2, v3, hi, lo);
        *(uint2*)&W1hi[j * LDA + k0] = hi;
        *(uint2*)&W1lo[j * LDA + k0] = lo;
    }
    // ---- W2^T split: W2T[n=j][k] = W2[k][j] ----
    for (int f = tid; f < 1024; f += 256) {
        int j = f & 31, k0 = (f >> 5) * 4;
        float v0 = W2[(k0 + 0) * 32 + j];
        float v1 = W2[(k0 + 1) * 32 + j];
        float v2 = W2[(k0 + 2) * 32 + j];
        float v3 = W2[(k0 + 3) * 32 + j];
        uint2 hi, lo; split4(v0, v1, v2, v3, hi, lo);
        *(uint2*)&W2hi[j * LDA + k0] = hi;
        *(uint2*)&W2lo[j * LDA + k0] = lo;
    }
    // ---- x tile split: A[row][k] ----
    for (int f = tid; f < 4096; f += 256) {
        int row = f >> 5, c0 = (f & 31) * 4;
        int r = row0 + row;
        float4 v = (r < N) ? ((const float4*)x)[(size_t)r * 32 + (c0 >> 2)]
                           : make_float4(0.f, 0.f, 0.f, 0.f);
        uint2 hi, lo; split4(v.x, v.y, v.z, v.w, hi, lo);
        *(uint2*)&Ahi[row * LDA + c0] = hi;
        *(uint2*)&Alo[row * LDA + c0] = lo;
    }
    __syncthreads();

    // ---- GEMM1: D1 = A @ W1T (split bf16, 3 products, fp32 accum) ----
    // warp grid: 4 (M: 32 rows) x 2 (N: 64 cols); per warp 2x4 16x16 tiles
    {
        const int wm = wid >> 1, wn = wid & 1;
        const int m0 = wm * 32, n0 = wn * 64;
        wmma::fragment<wmma::accumulator, 16, 16, 16, float> acc[2][4];
#pragma unroll
        for (int i = 0; i < 2; i++)
#pragma unroll
            for (int j = 0; j < 4; j++) wmma::fill_fragment(acc[i][j], 0.f);

#pragma unroll
        for (int kk = 0; kk < 8; kk++) {
            const int k0 = kk * 16;
            wmma::fragment<wmma::matrix_a, 16, 16, 16, __nv_bfloat16, wmma::row_major> ah[2], al[2];
#pragma unroll
            for (int i = 0; i < 2; i++) {
                wmma::load_matrix_sync(ah[i], &Ahi[(m0 + i * 16) * LDA + k0], LDA);
                wmma::load_matrix_sync(al[i], &Alo[(m0 + i * 16) * LDA + k0], LDA);
            }
#pragma unroll
            for (int j = 0; j < 4; j++) {
                wmma::fragment<wmma::matrix_b, 16, 16, 16, __nv_bfloat16, wmma::col_major> bh, bl;
                wmma::load_matrix_sync(bh, &W1hi[(n0 + j * 16) * LDA + k0], LDA);
                wmma::load_matrix_sync(bl, &W1lo[(n0 + j * 16) * LDA + k0], LDA);
#pragma unroll
                for (int i = 0; i < 2; i++) {
                    wmma::mma_sync(acc[i][j], ah[i], bh, acc[i][j]);
                    wmma::mma_sync(acc[i][j], ah[i], bl, acc[i][j]);
                    wmma::mma_sync(acc[i][j], al[i], bh, acc[i][j]);
                }
            }
        }
        __syncthreads();  // W1 region dead -> becomes D
#pragma unroll
        for (int i = 0; i < 2; i++)
#pragma unroll
            for (int j = 0; j < 4; j++)
                wmma::store_matrix_sync(&DW[(m0 + i * 16) * LDD + n0 + j * 16], acc[i][j],
                                        LDD, wmma::mem_row_major);
    }
    __syncthreads();

    // ---- epilogue1: h = relu(D1 + b1) -> split back into A buffers ----
    {
        const int row = tid >> 1, c0base = (tid & 1) * 64;
#pragma unroll
        for (int g = 0; g < 16; g++) {
            int c0 = c0base + g * 4;
            float4 d = *(const float4*)&DW[row * LDD + c0];
            float h0 = fmaxf(d.x + b1s[c0 + 0], 0.f);
            float h1 = fmaxf(d.y + b1s[c0 + 1], 0.f);
            float h2 = fmaxf(d.z + b1s[c0 + 2], 0.f);
            float h3 = fmaxf(d.w + b1s[c0 + 3], 0.f);
            uint2 hi, lo; split4(h0, h1, h2, h3, hi, lo);
            *(uint2*)&Ahi[row * LDA + c0] = hi;
            *(uint2*)&Alo[row * LDA + c0] = lo;
        }
    }
    __syncthreads();

    // ---- GEMM2: D2 = H @ W2T (128x32), one 16-row tile per warp ----
    {
        const int m0 = wid * 16;
        wmma::fragment<wmma::accumulator, 16, 16, 16, float> acc[2];
        wmma::fill_fragment(acc[0], 0.f);
        wmma::fill_fragment(acc[1], 0.f);
#pragma unroll
        for (int kk = 0; kk < 8; kk++) {
            const int k0 = kk * 16;
            wmma::fragment<wmma::matrix_a, 16, 16, 16, __nv_bfloat16, wmma::row_major> ah, al;
            wmma::load_matrix_sync(ah, &Ahi[m0 * LDA + k0], LDA);
            wmma::load_matrix_sync(al, &Alo[m0 * LDA + k0], LDA);
#pragma unroll
            for (int j = 0; j < 2; j++) {
                wmma::fragment<wmma::matrix_b, 16, 16, 16, __nv_bfloat16, wmma::col_major> bh, bl;
                wmma::load_matrix_sync(bh, &W2hi[(j * 16) * LDA + k0], LDA);
                wmma::load_matrix_sync(bl, &W2lo[(j * 16) * LDA + k0], LDA);
                wmma::mma_sync(acc[j], ah, bh, acc[j]);
                wmma::mma_sync(acc[j], ah, bl, acc[j]);
                wmma::mma_sync(acc[j], al, bh, acc[j]);
            }
        }
        __syncthreads();  // D1 reads done; reuse DW for D2
        wmma::store_matrix_sync(&DW[m0 * LDD2 + 0],  acc[0], LDD2, wmma::mem_row_major);
        wmma::store_matrix_sync(&DW[m0 * LDD2 + 16], acc[1], LDD2, wmma::mem_row_major);
    }
    __syncthreads();

    // ---- epilogue2: logits = (D2 + b2) * scaling -> g_L ----
    if (tid < 128) {
        const int grow = row0 + tid;
        if (grow < N) {
            float sc = __ldg(scaling);
#pragma unroll
            for (int q = 0; q < 8; q++) {
                float4 d = *(const float4*)&DW[tid * LDD2 + q * 4];
                float4 o;
                o.x = (d.x + b2s[q * 4 + 0]) * sc;
                o.y = (d.y + b2s[q * 4 + 1]) * sc;
                o.z = (d.z + b2s[q * 4 + 2]) * sc;
                o.w = (d.w + b2s[q * 4 + 3]) * sc;
                ((float4*)&g_L[(size_t)grow * 32])[q] = o;
            }
        }
    }
}

// ---------------- software grid barrier (all blocks resident) ----------------
__device__ __forceinline__ void grid_barrier(unsigned int nb)
{
    __syncthreads();
    if (threadIdx.x == 0) {
        __threadfence();
        unsigned int gen = *(volatile unsigned int*)&g_gen;
        if (atomicAdd(&g_arrive, 1u) == nb - 1u) {
            g_arrive = 0u;
            __threadfence();
            *(volatile unsigned int*)&g_gen = gen + 1u;
        } else {
            while (*(volatile unsigned int*)&g_gen == gen) { __nanosleep(64); }
        }
        __threadfence();
    }
    __syncthreads();
}

// ---------------- persistent fused Sinkhorn + pooling ----------------
#define EPAD 36
__global__ void __launch_bounds__(256, 1)
k_sinkpool(const float* __restrict__ x, const int* __restrict__ batch,
           float* __restrict__ out, int N, int rpb, unsigned int nb, float NK)
{
    extern __shared__ float smf[];
    float* E   = smf;                        // [rpb][EPAD]
    float* r   = E + (size_t)rpb * EPAD;     // [rpb]
    float* c   = r + rpb;                    // [32]
    float* red = c + 32;                     // [8][33]
    float* xs  = red + 8 * 33;               // [8][128]
    float* ss  = xs + 8 * 128;               // [8][32]
    int*   bs  = (int*)(ss + 8 * 32);        // [8]

    const int tid  = threadIdx.x;
    const int lane = tid & 31;
    const int wid  = tid >> 5;
    const int n0   = blockIdx.x * rpb;
    const int cnt  = max(0, min(rpb, N - n0));

    for (int idx = tid * 4; idx < cnt * 32; idx += 256 * 4) {
        float4 v = *(const float4*)&g_L[(size_t)n0 * 32 + idx];
        int row = idx >> 5, k = idx & 31;
        *(float4*)&E[row * EPAD + k] = v;
    }
    if (tid < 32) c[tid] = 1.f;
    __syncthreads();

    // E = exp(L - rowmax)
    for (int row = tid; row < cnt; row += 256) {
        float* Er = &E[row * EPAD];
        float er[32];
#pragma unroll
        for (int q = 0; q < 8; q++) {
            float4 t = *(const float4*)(Er + 4 * q);
            er[4*q] = t.x; er[4*q+1] = t.y; er[4*q+2] = t.z; er[4*q+3] = t.w;
        }
        float m = er[0];
#pragma unroll
        for (int k = 1; k < 32; k++) m = fmaxf(m, er[k]);
#pragma unroll
        for (int q = 0; q < 8; q++) {
            float4 t;
            t.x = __expf(er[4*q] - m);   t.y = __expf(er[4*q+1] - m);
            t.z = __expf(er[4*q+2] - m); t.w = __expf(er[4*q+3] - m);
            *(float4*)(Er + 4 * q) = t;
        }
    }
    __syncthreads();

    for (int it = 0; it < ITERS; it++) {
        float tl[32];
#pragma unroll
        for (int k = 0; k < 32; k++) tl[k] = 0.f;

        for (int row = tid; row < cnt; row += 256) {
            const float* Er = &E[row * EPAD];
            float er[32];
#pragma unroll
            for (int q = 0; q < 8; q++) {
                float4 t = *(const float4*)(Er + 4 * q);
                er[4*q] = t.x; er[4*q+1] = t.y; er[4*q+2] = t.z; er[4*q+3] = t.w;
            }
            float s = 0.f;
#pragma unroll
            for (int k = 0; k < 32; k++) s = fmaf(er[k], c[k], s);
            float rr = 1.0f / s;
            r[row] = rr;
#pragma unroll
            for (int k = 0; k < 32; k++) tl[k] = fmaf(er[k], rr, tl[k]);
        }

        float mine = 0.f;
#pragma unroll
        for (int k = 0; k < 32; k++) {
            float v = tl[k];
            v += __shfl_xor_sync(0xffffffffu, v, 16);
            v += __shfl_xor_sync(0xffffffffu, v, 8);
            v += __shfl_xor_sync(0xffffffffu, v, 4);
            v += __shfl_xor_sync(0xffffffffu, v, 2);
            v += __shfl_xor_sync(0xffffffffu, v, 1);
            if (lane == k) mine = v;
        }
        red[wid * 33 + lane] = mine;
        __syncthreads();
        if (tid < 32) {
            float s = 0.f;
#pragma unroll
            for (int w = 0; w < 8; w++) s += red[w * 33 + tid];
            atomicAdd(&g_t[it][tid], s);
        }

        grid_barrier(nb);

        if (tid < 32) c[tid] = NK / __ldcg(&g_t[it][tid]);
        __syncthreads();
    }

    // pooling
    const int kg = tid >> 5;
    const int cg = tid & 31;
    float acc[4][4];
#pragma unroll
    for (int i = 0; i < 4; i++)
#pragma unroll
        for (int j = 0; j < 4; j++) acc[i][j] = 0.f;
    int cur_b = -1;

    for (int s0 = 0; s0 < cnt; s0 += 8) {
        int nr = min(8, cnt - s0);
        __syncthreads();
        for (int f = tid; f < nr * 32; f += 256) {
            int rr = f >> 5, q = f & 31;
            ((float4*)(xs + rr * 128))[q] = ((const float4*)x)[(size_t)(n0 + s0 + rr) * 32 + q];
        }
        for (int f = tid; f < nr * 32; f += 256) {
            int rr = f >> 5, k = f & 31;
            ss[rr * 32 + k] = E[(s0 + rr) * EPAD + k] * r[s0 + rr] * c[k];
        }
        if (tid < nr) bs[tid] = batch[n0 + s0 + tid];
        __syncthreads();

        for (int rr = 0; rr < nr; rr++) {
            int bn = bs[rr];
            if (bn != cur_b) {
                if (cur_b >= 0) {
#pragma unroll
                    for (int i = 0; i < 4; i++)
#pragma unroll
                        for (int j = 0; j < 4; j++) {
                            atomicAdd(&out[((cur_b * 32 + kg * 4 + i) << 7) + cg * 4 + j], acc[i][j]);
                            acc[i][j] = 0.f;
                        }
                }
                cur_b = bn;
            }
            float4 sv = *(const float4*)&ss[rr * 32 + kg * 4];
            float4 xv = *(const float4*)&xs[rr * 128 + cg * 4];
            float svv[4] = {sv.x, sv.y, sv.z, sv.w};
            float xvv[4] = {xv.x, xv.y, xv.z, xv.w};
#pragma unroll
            for (int i = 0; i < 4; i++)
#pragma unroll
                for (int j = 0; j < 4; j++)
                    acc[i][j] = fmaf(svv[i], xvv[j], acc[i][j]);
        }
    }
    if (cur_b >= 0) {
#pragma unroll
        for (int i = 0; i < 4; i++)
#pragma unroll
            for (int j = 0; j < 4; j++)
                atomicAdd(&out[((cur_b * 32 + kg * 4 + i) << 7) + cg * 4 + j], acc[i][j]);
    }
}

// ---------------- launch ----------------
extern "C" void kernel_launch(void* const* d_in, const int* in_sizes, int n_in,
                              void* d_out, int out_size)
{
    const float* x       = (const float*)d_in[0];
    const int*   batch   = (const int*)d_in[1];
    const float* W1      = (const float*)d_in[2];
    const float* b1      = (const float*)d_in[3];
    const float* W2      = (const float*)d_in[4];
    const float* b2      = (const float*)d_in[5];
    const float* scaling = (const float*)d_in[6];

    const int N = in_sizes[0] / C_DIM;

    int dev = 0, nsm = 148;
    cudaGetDevice(&dev);
    cudaDeviceGetAttribute(&nsm, cudaDevAttrMultiProcessorCount, dev);
    unsigned int nb = (unsigned int)nsm;
    int rpb = (N + (int)nb - 1) / (int)nb;
    size_t smem2 = ((size_t)rpb * (EPAD + 1) + 32 + 8 * 33 + 8 * 128 + 8 * 32 + 16) * 4;

    cudaFuncSetAttribute(k_logits_tc, cudaFuncAttributeMaxDynamicSharedMemorySize, SMEM_TC);
    cudaFuncSetAttribute(k_sinkpool, cudaFuncAttributeMaxDynamicSharedMemorySize, (int)smem2);

    void* gt_addr = nullptr;
    cudaGetSymbolAddress(&gt_addr, g_t);
    cudaMemsetAsync(gt_addr, 0, sizeof(float) * ITERS * K_DIM);

    k_logits_tc<<<(N + 127) / 128, 256, SMEM_TC>>>(x, W1, b1, W2, b2, scaling, N);

    cudaMemsetAsync(d_out, 0, (size_t)out_size * sizeof(float));

    const float NK = (float)N / (float)K_DIM + 1e-9f;
    k_sinkpool<<<nb, 256, smem2>>>(x, batch, (float*)d_out, N, rpb, nb, NK);
}

// round 5
// speedup vs baseline: 2.5456x; 1.3343x over previous
#include <cuda_runtime.h>
#include <cuda_bf16.h>
#include <mma.h>
#include <math.h>
#include <stdint.h>

using namespace nvcuda;

// Problem constants (dataset-fixed): C=128, K=32, N=200000, B=16.
#define C_DIM 128
#define K_DIM 32
#define N_MAX 200704
#define ITERS 20

// ---------------- scratch ----------------
__device__ float g_L[(size_t)N_MAX * K_DIM];
__device__ float g_t[ITERS][K_DIM];
__device__ unsigned int g_arrive = 0;
__device__ unsigned int g_gen = 0;
__device__ __nv_bfloat16 g_W1hi[128 * 128], g_W1lo[128 * 128];  // [j][k] (transposed)
__device__ __nv_bfloat16 g_W2hi[32 * 128],  g_W2lo[32 * 128];   // [j][k]

// split 4 consecutive floats into hi/lo bf16x2 pairs
__device__ __forceinline__ void split4(float a, float b, float c, float d, uint2& hi, uint2& lo) {
    __nv_bfloat162 h0 = __floats2bfloat162_rn(a, b);
    __nv_bfloat162 h1 = __floats2bfloat162_rn(c, d);
    __nv_bfloat162 l0 = __floats2bfloat162_rn(a - __low2float(h0), b - __high2float(h0));
    __nv_bfloat162 l1 = __floats2bfloat162_rn(c - __low2float(h1), d - __high2float(h1));
    hi.x = *reinterpret_cast<uint32_t*>(&h0);
    hi.y = *reinterpret_cast<uint32_t*>(&h1);
    lo.x = *reinterpret_cast<uint32_t*>(&l0);
    lo.y = *reinterpret_cast<uint32_t*>(&l1);
}

// ---------------- one-time weight split (transposed [j][k]) ----------------
__global__ void k_splitw(const float* __restrict__ W1, const float* __restrict__ W2) {
    int t = blockIdx.x * 256 + threadIdx.x;
    if (t < 4096) {
        int j = t & 127, k0 = (t >> 7) << 2;
        float v0 = W1[(k0 + 0) * 128 + j], v1 = W1[(k0 + 1) * 128 + j];
        float v2 = W1[(k0 + 2) * 128 + j], v3 = W1[(k0 + 3) * 128 + j];
        uint2 hi, lo; split4(v0, v1, v2, v3, hi, lo);
        *(uint2*)&g_W1hi[j * 128 + k0] = hi;
        *(uint2*)&g_W1lo[j * 128 + k0] = lo;
    } else if (t < 5120) {
        int t2 = t - 4096;
        int j = t2 & 31, k0 = (t2 >> 5) << 2;
        float v0 = W2[(k0 + 0) * 32 + j], v1 = W2[(k0 + 1) * 32 + j];
        float v2 = W2[(k0 + 2) * 32 + j], v3 = W2[(k0 + 3) * 32 + j];
        uint2 hi, lo; split4(v0, v1, v2, v3, hi, lo);
        *(uint2*)&g_W2hi[j * 128 + k0] = hi;
        *(uint2*)&g_W2lo[j * 128 + k0] = lo;
    }
}

// ================= persistent wmma MLP -> logits =================
#define LDA 136
#define LDD 132
#define LDD2 36
#define OF_AHI  0
#define OF_ALO  (OF_AHI + 128 * LDA * 2)   // 34816
#define OF_W1HI (OF_ALO + 128 * LDA * 2)   // 69632
#define OF_W1LO (OF_W1HI + 128 * LDA * 2)  // 104448
#define OF_W2HI (OF_W1LO + 128 * LDA * 2)  // 139264
#define OF_W2LO (OF_W2HI + 32 * LDA * 2)   // 147968
#define OF_D    (OF_W2LO + 32 * LDA * 2)   // 156672  (128x132 f32)
#define OF_B1   (OF_D + 128 * LDD * 4)     // 224256
#define OF_B2   (OF_B1 + 512)              // 224768
#define SMEM_TC (OF_B2 + 128)              // 224896

__global__ void __launch_bounds__(512, 1)
k_logits_tc(const float* __restrict__ x, const float* __restrict__ b1,
            const float* __restrict__ b2, const float* __restrict__ scaling,
            int N, int ntiles)
{
    extern __shared__ char sm[];
    __nv_bfloat16* Ahi = (__nv_bfloat16*)(sm + OF_AHI);
    __nv_bfloat16* Alo = (__nv_bfloat16*)(sm + OF_ALO);
    __nv_bfloat16* W1h = (__nv_bfloat16*)(sm + OF_W1HI);
    __nv_bfloat16* W1l = (__nv_bfloat16*)(sm + OF_W1LO);
    __nv_bfloat16* W2h = (__nv_bfloat16*)(sm + OF_W2HI);
    __nv_bfloat16* W2l = (__nv_bfloat16*)(sm + OF_W2LO);
    float* D   = (float*)(sm + OF_D);
    float* b1s = (float*)(sm + OF_B1);
    float* b2s = (float*)(sm + OF_B2);

    const int tid = threadIdx.x, wid = tid >> 5;
    const float sc = __ldg(scaling);

    // ---- stage weights once ----
    for (int f = tid; f < 2048; f += 512) {
        int j = f >> 4, q = f & 15;
        *(uint4*)&W1h[j * LDA + q * 8] = ((const uint4*)g_W1hi)[f];
        *(uint4*)&W1l[j * LDA + q * 8] = ((const uint4*)g_W1lo)[f];
    }
    for (int f = tid; f < 512; f += 512) {
        int j = f >> 4, q = f & 15;
        *(uint4*)&W2h[j * LDA + q * 8] = ((const uint4*)g_W2hi)[f];
        *(uint4*)&W2l[j * LDA + q * 8] = ((const uint4*)g_W2lo)[f];
    }
    if (tid < 128) b1s[tid] = b1[tid];
    else if (tid < 160) b2s[tid - 128] = b2[tid - 128];
    __syncthreads();

    for (int t = blockIdx.x; t < ntiles; t += gridDim.x) {
        const int row0 = t << 7;

        // ---- x tile load + split ----
        for (int f = tid; f < 4096; f += 512) {
            int row = f >> 5, c0 = (f & 31) << 2;
            int r = row0 + row;
            float4 v = (r < N) ? ((const float4*)x)[(size_t)r * 32 + (c0 >> 2)]
                               : make_float4(0.f, 0.f, 0.f, 0.f);
            uint2 hi, lo; split4(v.x, v.y, v.z, v.w, hi, lo);
            *(uint2*)&Ahi[row * LDA + c0] = hi;
            *(uint2*)&Alo[row * LDA + c0] = lo;
        }
        __syncthreads();

        // ---- GEMM1: D1 = A @ W1T (16 warps: 4m x 4n, each 2x2 tiles) ----
        {
            const int wm = wid >> 2, wn = wid & 3;
            const int m0 = wm * 32, n0 = wn * 32;
            wmma::fragment<wmma::accumulator, 16, 16, 16, float> acc[2][2];
#pragma unroll
            for (int i = 0; i < 2; i++)
#pragma unroll
                for (int j = 0; j < 2; j++) wmma::fill_fragment(acc[i][j], 0.f);
#pragma unroll
            for (int kk = 0; kk < 8; kk++) {
                const int k0 = kk * 16;
                wmma::fragment<wmma::matrix_a, 16, 16, 16, __nv_bfloat16, wmma::row_major> ah[2], al[2];
#pragma unroll
                for (int i = 0; i < 2; i++) {
                    wmma::load_matrix_sync(ah[i], &Ahi[(m0 + i * 16) * LDA + k0], LDA);
                    wmma::load_matrix_sync(al[i], &Alo[(m0 + i * 16) * LDA + k0], LDA);
                }
#pragma unroll
                for (int j = 0; j < 2; j++) {
                    wmma::fragment<wmma::matrix_b, 16, 16, 16, __nv_bfloat16, wmma::col_major> bh, bl;
                    wmma::load_matrix_sync(bh, &W1h[(n0 + j * 16) * LDA + k0], LDA);
                    wmma::load_matrix_sync(bl, &W1l[(n0 + j * 16) * LDA + k0], LDA);
#pragma unroll
                    for (int i = 0; i < 2; i++) {
                        wmma::mma_sync(acc[i][j], ah[i], bh, acc[i][j]);
                        wmma::mma_sync(acc[i][j], ah[i], bl, acc[i][j]);
                        wmma::mma_sync(acc[i][j], al[i], bh, acc[i][j]);
                    }
                }
            }
#pragma unroll
            for (int i = 0; i < 2; i++)
#pragma unroll
                for (int j = 0; j < 2; j++)
                    wmma::store_matrix_sync(&D[(m0 + i * 16) * LDD + n0 + j * 16], acc[i][j],
                                            LDD, wmma::mem_row_major);
        }
        __syncthreads();

        // ---- epilogue1: h = relu(D1+b1) -> re-split into A ----
        {
            const int row = tid >> 2, cb = (tid & 3) * 32;
#pragma unroll
            for (int g = 0; g < 8; g++) {
                int c0 = cb + g * 4;
                float4 d = *(const float4*)&D[row * LDD + c0];
                float h0 = fmaxf(d.x + b1s[c0 + 0], 0.f);
                float h1 = fmaxf(d.y + b1s[c0 + 1], 0.f);
                float h2 = fmaxf(d.z + b1s[c0 + 2], 0.f);
                float h3 = fmaxf(d.w + b1s[c0 + 3], 0.f);
                uint2 hi, lo; split4(h0, h1, h2, h3, hi, lo);
                *(uint2*)&Ahi[row * LDA + c0] = hi;
                *(uint2*)&Alo[row * LDA + c0] = lo;
            }
        }
        __syncthreads();

        // ---- GEMM2: D2 = H @ W2T (16 warps: 8m x 2n) ----
        {
            const int mt = wid >> 1, nt = wid & 1;
            const int m0 = mt * 16, n0 = nt * 16;
            wmma::fragment<wmma::accumulator, 16, 16, 16, float> acc2;
            wmma::fill_fragment(acc2, 0.f);
#pragma unroll
            for (int kk = 0; kk < 8; kk++) {
                const int k0 = kk * 16;
                wmma::fragment<wmma::matrix_a, 16, 16, 16, __nv_bfloat16, wmma::row_major> ah, al;
                wmma::fragment<wmma::matrix_b, 16, 16, 16, __nv_bfloat16, wmma::col_major> bh, bl;
                wmma::load_matrix_sync(ah, &Ahi[m0 * LDA + k0], LDA);
                wmma::load_matrix_sync(al, &Alo[m0 * LDA + k0], LDA);
                wmma::load_matrix_sync(bh, &W2h[n0 * LDA + k0], LDA);
                wmma::load_matrix_sync(bl, &W2l[n0 * LDA + k0], LDA);
                wmma::mma_sync(acc2, ah, bh, acc2);
                wmma::mma_sync(acc2, ah, bl, acc2);
                wmma::mma_sync(acc2, al, bh, acc2);
            }
            wmma::store_matrix_sync(&D[m0 * LDD2 + n0], acc2, LDD2, wmma::mem_row_major);
        }
        __syncthreads();

        // ---- epilogue2: logits = (D2+b2)*sc -> g_L ----
        {
            const int row = tid >> 2, c0 = (tid & 3) * 8;
            const int grow = row0 + row;
            if (grow < N) {
                float4 d0 = *(const float4*)&D[row * LDD2 + c0];
                float4 d1 = *(const float4*)&D[row * LDD2 + c0 + 4];
                float4 o0 = make_float4((d0.x + b2s[c0 + 0]) * sc, (d0.y + b2s[c0 + 1]) * sc,
                                        (d0.z + b2s[c0 + 2]) * sc, (d0.w + b2s[c0 + 3]) * sc);
                float4 o1 = make_float4((d1.x + b2s[c0 + 4]) * sc, (d1.y + b2s[c0 + 5]) * sc,
                                        (d1.z + b2s[c0 + 6]) * sc, (d1.w + b2s[c0 + 7]) * sc);
                *(float4*)&g_L[(size_t)grow * 32 + c0] = o0;
                *(float4*)&g_L[(size_t)grow * 32 + c0 + 4] = o1;
            }
        }
        __syncthreads();
    }
}

// ---------------- software grid barrier ----------------
__device__ __forceinline__ void grid_barrier(unsigned int nb)
{
    __syncthreads();
    if (threadIdx.x == 0) {
        __threadfence();
        unsigned int gen = *(volatile unsigned int*)&g_gen;
        if (atomicAdd(&g_arrive, 1u) == nb - 1u) {
            g_arrive = 0u;
            __threadfence();
            *(volatile unsigned int*)&g_gen = gen + 1u;
        } else {
            while (*(volatile unsigned int*)&g_gen == gen) { __nanosleep(64); }
        }
        __threadfence();
    }
    __syncthreads();
}

// ---------------- persistent fused Sinkhorn + wmma pooling ----------------
// E stored transposed: ET[k][RP] (RP odd => conflict-free for every pattern).
__global__ void __launch_bounds__(512, 1)
k_sinkpool(const float* __restrict__ x, const int* __restrict__ batch,
           float* __restrict__ out, int N, int rpb, int RP, unsigned int nb, float NK)
{
    extern __shared__ float smf[];
    float* ET = smf;                    // [32][RP]
    float* r  = smf + 32 * RP;          // [rpb]
    float* c  = r + rpb;                // [32]
    float* un = c + 32;                 // union scratch
    float* red = un;                    // [16][33] (iteration phase)
    __nv_bfloat16* shi = (__nv_bfloat16*)un;      // pool phase overlay
    __nv_bfloat16* slo = shi + 16 * 40;
    __nv_bfloat16* xhi = slo + 16 * 40;
    __nv_bfloat16* xlo = xhi + 16 * 136;
    float* Dp = (float*)(xlo + 16 * 136);          // [32][132]
    int*   bs = (int*)(Dp + 32 * 132);             // [16]

    const int tid  = threadIdx.x;
    const int lane = tid & 31;
    const int wid  = tid >> 5;
    const int n0   = blockIdx.x * rpb;
    const int cnt  = max(0, min(rpb, N - n0));

    // ---- load logits transposed into ET ----
    for (int f = tid; f < cnt * 8; f += 512) {
        int row = f >> 3, q = (f & 7) << 2;
        float4 v = *(const float4*)&g_L[(size_t)(n0 + row) * 32 + q];
        ET[(q + 0) * RP + row] = v.x;
        ET[(q + 1) * RP + row] = v.y;
        ET[(q + 2) * RP + row] = v.z;
        ET[(q + 3) * RP + row] = v.w;
    }
    if (tid < 32) c[tid] = 1.f;
    __syncthreads();

    // ---- E = exp(L - rowmax) ----
    for (int row = tid; row < cnt; row += 512) {
        float e[32];
        float m = -1e30f;
#pragma unroll
        for (int k = 0; k < 32; k++) { e[k] = ET[k * RP + row]; m = fmaxf(m, e[k]); }
#pragma unroll
        for (int k = 0; k < 32; k++) ET[k * RP + row] = __expf(e[k] - m);
    }
    __syncthreads();

    // ---- 20 Sinkhorn iterations ----
    for (int it = 0; it < ITERS; it++) {
        float cr[32];
#pragma unroll
        for (int k = 0; k < 32; k++) cr[k] = c[k];

        // pass A: r[row] = 1 / sum_k E*c
        for (int row = tid; row < cnt; row += 512) {
            float s = 0.f;
#pragma unroll
            for (int k = 0; k < 32; k++) s = fmaf(ET[k * RP + row], cr[k], s);
            r[row] = 1.0f / s;
        }
        __syncthreads();

        // pass B: lane-owns-k warp-cooperative column sums (no shuffles)
        {
            int cpw = (cnt + 15) >> 4;
            int rs = wid * cpw, re = min(rs + cpw, cnt);
            float tlk = 0.f;
            const float* ETk = &ET[lane * RP];
            for (int row = rs; row < re; row++)
                tlk = fmaf(ETk[row], r[row], tlk);
            red[wid * 33 + lane] = tlk;
        }
        __syncthreads();
        if (tid < 32) {
            float s = 0.f;
#pragma unroll
            for (int w = 0; w < 16; w++) s += red[w * 33 + tid];
            atomicAdd(&g_t[it][tid], s);
        }

        grid_barrier(nb);

        if (tid < 32) c[tid] = NK / __ldcg(&g_t[it][tid]);
        __syncthreads();
    }

    // ---- pooling: out[b] += S^T X via wmma (split bf16), fragment-resident acc ----
    const int mt = wid & 1;   // m-tile (k-cluster dim, 2 x 16)
    const int nt = wid >> 1;  // n-tile (c dim, 8 x 16)
    wmma::fragment<wmma::accumulator, 16, 16, 16, float> pacc;
    wmma::fill_fragment(pacc, 0.f);
    int cur_b = -1;

#define POOL_FLUSH(BB) do { \
    __syncthreads(); \
    wmma::store_matrix_sync(&Dp[(mt * 16) * 132 + nt * 16], pacc, 132, wmma::mem_row_major); \
    __syncthreads(); \
    for (int f2 = tid; f2 < 4096; f2 += 512) { \
        int mm = f2 >> 7, cc2 = f2 & 127; \
        atomicAdd(&out[(((BB) * 32 + mm) << 7) + cc2], Dp[mm * 132 + cc2]); \
    } \
    wmma::fill_fragment(pacc, 0.f); \
} while (0)

    for (int s0 = 0; s0 < cnt; s0 += 16) {
        const int nr = min(16, cnt - s0);
        __syncthreads();
        // build X chunk (hi/lo), zero-padded rows
        {
            int row = tid >> 5, q = tid & 31;
            uint2 hi = make_uint2(0u, 0u), lo = make_uint2(0u, 0u);
            if (row < nr) {
                float4 v = ((const float4*)x)[(size_t)(n0 + s0 + row) * 32 + q];
                split4(v.x, v.y, v.z, v.w, hi, lo);
            }
            *(uint2*)&xhi[row * 136 + q * 4] = hi;
            *(uint2*)&xlo[row * 136 + q * 4] = lo;
        }
        // build S chunk (hi/lo), zero-padded rows
        {
            int row = tid >> 5, k = tid & 31;
            float sv = 0.f;
            if (row < nr) sv = ET[k * RP + s0 + row] * r[s0 + row] * c[k];
            __nv_bfloat16 h = __float2bfloat16(sv);
            shi[row * 40 + k] = h;
            slo[row * 40 + k] = __float2bfloat16(sv - __bfloat162float(h));
            if (k == 0) bs[row] = (row < nr) ? batch[n0 + s0 + row] : -1;
        }
        __syncthreads();

        int pos = 0;
        while (pos < nr) {
            int seg = bs[pos];
            int e = pos + 1;
            while (e < nr && bs[e] == seg) e++;
            if (seg != cur_b) {
                if (cur_b >= 0) POOL_FLUSH(cur_b);
                cur_b = seg;
            }
            bool full = (pos == 0 && e == nr);
            if (!full) {  // rare: rebuild masked S
                __syncthreads();
                int row = tid >> 5, k = tid & 31;
                float sv = 0.f;
                if (row >= pos && row < e) sv = ET[k * RP + s0 + row] * r[s0 + row] * c[k];
                __nv_bfloat16 h = __float2bfloat16(sv);
                shi[row * 40 + k] = h;
                slo[row * 40 + k] = __float2bfloat16(sv - __bfloat162float(h));
                __syncthreads();
            }
            wmma::fragment<wmma::matrix_a, 16, 16, 16, __nv_bfloat16, wmma::col_major> sa_h, sa_l;
            wmma::fragment<wmma::matrix_b, 16, 16, 16, __nv_bfloat16, wmma::row_major> xb_h, xb_l;
            wmma::load_matrix_sync(sa_h, &shi[mt * 16], 40);
            wmma::load_matrix_sync(sa_l, &slo[mt * 16], 40);
            wmma::load_matrix_sync(xb_h, &xhi[nt * 16], 136);
            wmma::load_matrix_sync(xb_l, &xlo[nt * 16], 136);
            wmma::mma_sync(pacc, sa_h, xb_h, pacc);
            wmma::mma_sync(pacc, sa_h, xb_l, pacc);
            wmma::mma_sync(pacc, sa_l, xb_h, pacc);
            pos = e;
        }
    }
    if (cur_b >= 0) POOL_FLUSH(cur_b);
#undef POOL_FLUSH
}

// ---------------- launch ----------------
extern "C" void kernel_launch(void* const* d_in, const int* in_sizes, int n_in,
                              void* d_out, int out_size)
{
    const float* x       = (const float*)d_in[0];
    const int*   batch   = (const int*)d_in[1];
    const float* W1      = (const float*)d_in[2];
    const float* b1      = (const float*)d_in[3];
    const float* W2      = (const float*)d_in[4];
    const float* b2      = (const float*)d_in[5];
    const float* scaling = (const float*)d_in[6];

    const int N = in_sizes[0] / C_DIM;

    int dev = 0, nsm = 148;
    cudaGetDevice(&dev);
    cudaDeviceGetAttribute(&nsm, cudaDevAttrMultiProcessorCount, dev);
    const int nb = nsm;
    const int rpb = (N + nb - 1) / nb;
    const int RP = rpb + ((rpb & 1) ? 2 : 1);  // odd leading dim
    const size_t smem2 = ((size_t)32 * RP + rpb + 32 + 7056 + 64) * 4;
    const int ntiles = (N + 127) >> 7;
    const int gl = ntiles < nsm ? ntiles : nsm;

    cudaFuncSetAttribute(k_logits_tc, cudaFuncAttributeMaxDynamicSharedMemorySize, SMEM_TC);
    cudaFuncSetAttribute(k_sinkpool, cudaFuncAttributeMaxDynamicSharedMemorySize, (int)smem2);

    void* gt_addr = nullptr;
    cudaGetSymbolAddress(&gt_addr, g_t);
    cudaMemsetAsync(gt_addr, 0, sizeof(float) * ITERS * K_DIM);

    k_splitw<<<20, 256>>>(W1, W2);
    k_logits_tc<<<gl, 512, SMEM_TC>>>(x, b1, b2, scaling, N, ntiles);

    cudaMemsetAsync(d_out, 0, (size_t)out_size * sizeof(float));

    const float NK = (float)N / (float)K_DIM + 1e-9f;
    k_sinkpool<<<nb, 512, smem2>>>(x, batch, (float*)d_out, N, rpb, RP, (unsigned)nb, NK);
}

// round 6
// speedup vs baseline: 2.9291x; 1.1506x over previous
#include <cuda_runtime.h>
#include <cuda_bf16.h>
#include <mma.h>
#include <math.h>
#include <stdint.h>

using namespace nvcuda;

// Problem constants (dataset-fixed): C=128, K=32, N=200000, B=16.
#define C_DIM 128
#define K_DIM 32
#define N_MAX 200704
#define ITERS 20

// ---------------- scratch ----------------
__device__ float g_L[(size_t)N_MAX * K_DIM];
__device__ float g_t[ITERS][K_DIM];
__device__ unsigned int g_arrive = 0;
__device__ unsigned int g_gen = 0;

// split 4 consecutive floats into hi/lo bf16x2 pairs
__device__ __forceinline__ void split4(float a, float b, float c, float d, uint2& hi, uint2& lo) {
    __nv_bfloat162 h0 = __floats2bfloat162_rn(a, b);
    __nv_bfloat162 h1 = __floats2bfloat162_rn(c, d);
    __nv_bfloat162 l0 = __floats2bfloat162_rn(a - __low2float(h0), b - __high2float(h0));
    __nv_bfloat162 l1 = __floats2bfloat162_rn(c - __low2float(h1), d - __high2float(h1));
    hi.x = *reinterpret_cast<uint32_t*>(&h0);
    hi.y = *reinterpret_cast<uint32_t*>(&h1);
    lo.x = *reinterpret_cast<uint32_t*>(&l0);
    lo.y = *reinterpret_cast<uint32_t*>(&l1);
}

// ================= persistent wmma MLP -> logits =================
#define LDA 136
#define LDD 132
#define LDD2 36
#define OF_AHI  0
#define OF_ALO  (OF_AHI + 128 * LDA * 2)
#define OF_W1HI (OF_ALO + 128 * LDA * 2)
#define OF_W1LO (OF_W1HI + 128 * LDA * 2)
#define OF_W2HI (OF_W1LO + 128 * LDA * 2)
#define OF_W2LO (OF_W2HI + 32 * LDA * 2)
#define OF_D    (OF_W2LO + 32 * LDA * 2)
#define OF_B1   (OF_D + 128 * LDD * 4)
#define OF_B2   (OF_B1 + 512)
#define SMEM_TC (OF_B2 + 128)

__global__ void __launch_bounds__(512, 1)
k_logits_tc(const float* __restrict__ x, const float* __restrict__ W1,
            const float* __restrict__ b1, const float* __restrict__ W2,
            const float* __restrict__ b2, const float* __restrict__ scaling,
            int N, int ntiles)
{
    extern __shared__ char sm[];
    __nv_bfloat16* Ahi = (__nv_bfloat16*)(sm + OF_AHI);
    __nv_bfloat16* Alo = (__nv_bfloat16*)(sm + OF_ALO);
    __nv_bfloat16* W1h = (__nv_bfloat16*)(sm + OF_W1HI);
    __nv_bfloat16* W1l = (__nv_bfloat16*)(sm + OF_W1LO);
    __nv_bfloat16* W2h = (__nv_bfloat16*)(sm + OF_W2HI);
    __nv_bfloat16* W2l = (__nv_bfloat16*)(sm + OF_W2LO);
    float* D   = (float*)(sm + OF_D);
    float* b1s = (float*)(sm + OF_B1);
    float* b2s = (float*)(sm + OF_B2);

    const int tid = threadIdx.x, wid = tid >> 5;
    const float sc = __ldg(scaling);

    // ---- split weights into smem (per block, coalesced in j, L2-shared) ----
    for (int f = tid; f < 4096; f += 512) {
        int j = f & 127, k0 = (f >> 7) << 2;
        float v0 = W1[(k0 + 0) * 128 + j], v1 = W1[(k0 + 1) * 128 + j];
        float v2 = W1[(k0 + 2) * 128 + j], v3 = W1[(k0 + 3) * 128 + j];
        uint2 hi, lo; split4(v0, v1, v2, v3, hi, lo);
        *(uint2*)&W1h[j * LDA + k0] = hi;
        *(uint2*)&W1l[j * LDA + k0] = lo;
    }
    for (int f = tid; f < 1024; f += 512) {
        int j = f & 31, k0 = (f >> 5) << 2;
        float v0 = W2[(k0 + 0) * 32 + j], v1 = W2[(k0 + 1) * 32 + j];
        float v2 = W2[(k0 + 2) * 32 + j], v3 = W2[(k0 + 3) * 32 + j];
        uint2 hi, lo; split4(v0, v1, v2, v3, hi, lo);
        *(uint2*)&W2h[j * LDA + k0] = hi;
        *(uint2*)&W2l[j * LDA + k0] = lo;
    }
    if (tid < 128) b1s[tid] = b1[tid];
    else if (tid < 160) b2s[tid - 128] = b2[tid - 128];
    __syncthreads();

    // ---- register prefetch of first tile ----
    float4 xbuf[8];
    int t = blockIdx.x;
    if (t < ntiles) {
        const int row0 = t << 7;
#pragma unroll
        for (int i = 0; i < 8; i++) {
            int f = tid + i * 512;
            int row = f >> 5, q = f & 31;
            int rr = row0 + row;
            xbuf[i] = (rr < N) ? ((const float4*)x)[(size_t)rr * 32 + q]
                               : make_float4(0.f, 0.f, 0.f, 0.f);
        }
    }

    for (; t < ntiles; t += gridDim.x) {
        const int row0 = t << 7;

        // ---- split prefetched tile into A ----
#pragma unroll
        for (int i = 0; i < 8; i++) {
            int f = tid + i * 512;
            int row = f >> 5, c0 = (f & 31) << 2;
            uint2 hi, lo; split4(xbuf[i].x, xbuf[i].y, xbuf[i].z, xbuf[i].w, hi, lo);
            *(uint2*)&Ahi[row * LDA + c0] = hi;
            *(uint2*)&Alo[row * LDA + c0] = lo;
        }
        __syncthreads();

        // ---- prefetch NEXT tile (LDGs overlap GEMM1) ----
        {
            int tn = t + gridDim.x;
            if (tn < ntiles) {
                const int rown = tn << 7;
#pragma unroll
                for (int i = 0; i < 8; i++) {
                    int f = tid + i * 512;
                    int row = f >> 5, q = f & 31;
                    int rr = rown + row;
                    xbuf[i] = (rr < N) ? ((const float4*)x)[(size_t)rr * 32 + q]
                                       : make_float4(0.f, 0.f, 0.f, 0.f);
                }
            }
        }

        // ---- GEMM1: D1 = A @ W1T (16 warps: 4m x 4n, each 2x2 tiles) ----
        {
            const int wm = wid >> 2, wn = wid & 3;
            const int m0 = wm * 32, n0 = wn * 32;
            wmma::fragment<wmma::accumulator, 16, 16, 16, float> acc[2][2];
#pragma unroll
            for (int i = 0; i < 2; i++)
#pragma unroll
                for (int j = 0; j < 2; j++) wmma::fill_fragment(acc[i][j], 0.f);
#pragma unroll
            for (int kk = 0; kk < 8; kk++) {
                const int k0 = kk * 16;
                wmma::fragment<wmma::matrix_a, 16, 16, 16, __nv_bfloat16, wmma::row_major> ah[2], al[2];
#pragma unroll
                for (int i = 0; i < 2; i++) {
                    wmma::load_matrix_sync(ah[i], &Ahi[(m0 + i * 16) * LDA + k0], LDA);
                    wmma::load_matrix_sync(al[i], &Alo[(m0 + i * 16) * LDA + k0], LDA);
                }
#pragma unroll
                for (int j = 0; j < 2; j++) {
                    wmma::fragment<wmma::matrix_b, 16, 16, 16, __nv_bfloat16, wmma::col_major> bh, bl;
                    wmma::load_matrix_sync(bh, &W1h[(n0 + j * 16) * LDA + k0], LDA);
                    wmma::load_matrix_sync(bl, &W1l[(n0 + j * 16) * LDA + k0], LDA);
#pragma unroll
                    for (int i = 0; i < 2; i++) {
                        wmma::mma_sync(acc[i][j], ah[i], bh, acc[i][j]);
                        wmma::mma_sync(acc[i][j], ah[i], bl, acc[i][j]);
                        wmma::mma_sync(acc[i][j], al[i], bh, acc[i][j]);
                    }
                }
            }
#pragma unroll
            for (int i = 0; i < 2; i++)
#pragma unroll
                for (int j = 0; j < 2; j++)
                    wmma::store_matrix_sync(&D[(m0 + i * 16) * LDD + n0 + j * 16], acc[i][j],
                                            LDD, wmma::mem_row_major);
        }
        __syncthreads();

        // ---- epilogue1: h = relu(D1+b1) -> re-split into A ----
        {
            const int row = tid >> 2, cb = (tid & 3) * 32;
#pragma unroll
            for (int g = 0; g < 8; g++) {
                int c0 = cb + g * 4;
                float4 d = *(const float4*)&D[row * LDD + c0];
                float h0 = fmaxf(d.x + b1s[c0 + 0], 0.f);
                float h1 = fmaxf(d.y + b1s[c0 + 1], 0.f);
                float h2 = fmaxf(d.z + b1s[c0 + 2], 0.f);
                float h3 = fmaxf(d.w + b1s[c0 + 3], 0.f);
                uint2 hi, lo; split4(h0, h1, h2, h3, hi, lo);
                *(uint2*)&Ahi[row * LDA + c0] = hi;
                *(uint2*)&Alo[row * LDA + c0] = lo;
            }
        }
        __syncthreads();

        // ---- GEMM2: D2 = H @ W2T (16 warps: 8m x 2n) ----
        {
            const int mt = wid >> 1, nt = wid & 1;
            const int m0 = mt * 16, n0 = nt * 16;
            wmma::fragment<wmma::accumulator, 16, 16, 16, float> acc2;
            wmma::fill_fragment(acc2, 0.f);
#pragma unroll
            for (int kk = 0; kk < 8; kk++) {
                const int k0 = kk * 16;
                wmma::fragment<wmma::matrix_a, 16, 16, 16, __nv_bfloat16, wmma::row_major> ah, al;
                wmma::fragment<wmma::matrix_b, 16, 16, 16, __nv_bfloat16, wmma::col_major> bh, bl;
                wmma::load_matrix_sync(ah, &Ahi[m0 * LDA + k0], LDA);
                wmma::load_matrix_sync(al, &Alo[m0 * LDA + k0], LDA);
                wmma::load_matrix_sync(bh, &W2h[n0 * LDA + k0], LDA);
                wmma::load_matrix_sync(bl, &W2l[n0 * LDA + k0], LDA);
                wmma::mma_sync(acc2, ah, bh, acc2);
                wmma::mma_sync(acc2, ah, bl, acc2);
                wmma::mma_sync(acc2, al, bh, acc2);
            }
            wmma::store_matrix_sync(&D[m0 * LDD2 + n0], acc2, LDD2, wmma::mem_row_major);
        }
        __syncthreads();

        // ---- epilogue2: logits = (D2+b2)*sc -> g_L ----
        {
            const int row = tid >> 2, c0 = (tid & 3) * 8;
            const int grow = row0 + row;
            if (grow < N) {
                float4 d0 = *(const float4*)&D[row * LDD2 + c0];
                float4 d1 = *(const float4*)&D[row * LDD2 + c0 + 4];
                float4 o0 = make_float4((d0.x + b2s[c0 + 0]) * sc, (d0.y + b2s[c0 + 1]) * sc,
                                        (d0.z + b2s[c0 + 2]) * sc, (d0.w + b2s[c0 + 3]) * sc);
                float4 o1 = make_float4((d1.x + b2s[c0 + 4]) * sc, (d1.y + b2s[c0 + 5]) * sc,
                                        (d1.z + b2s[c0 + 6]) * sc, (d1.w + b2s[c0 + 7]) * sc);
                *(float4*)&g_L[(size_t)grow * 32 + c0] = o0;
                *(float4*)&g_L[(size_t)grow * 32 + c0 + 4] = o1;
            }
        }
        __syncthreads();
    }
}

// ---------------- software grid barrier ----------------
__device__ __forceinline__ void grid_barrier(unsigned int nb)
{
    __syncthreads();
    if (threadIdx.x == 0) {
        __threadfence();
        unsigned int gen = *(volatile unsigned int*)&g_gen;
        if (atomicAdd(&g_arrive, 1u) == nb - 1u) {
            g_arrive = 0u;
            __threadfence();
            *(volatile unsigned int*)&g_gen = gen + 1u;
        } else {
            while (*(volatile unsigned int*)&g_gen == gen) { __nanosleep(64); }
        }
        __threadfence();
    }
    __syncthreads();
}

// ---------------- persistent fused Sinkhorn + wmma pooling ----------------
// E transposed: ET[k][RP], RP odd => conflict-free.
__global__ void __launch_bounds__(512)
k_sinkpool(const float* __restrict__ x, const int* __restrict__ batch,
           float* __restrict__ out, int N, int rpb, int RP, unsigned int nb, float NK)
{
    extern __shared__ float smf[];
    float* ET = smf;                    // [32][RP]
    float* r  = smf + 32 * RP;          // [rpb]
    float* c  = r + rpb;                // [32]
    float* un = c + 32;
    float* red = un;                    // [16][33]
    __nv_bfloat16* shi = (__nv_bfloat16*)un;
    __nv_bfloat16* slo = shi + 16 * 40;
    __nv_bfloat16* xhi = slo + 16 * 40;
    __nv_bfloat16* xlo = xhi + 16 * 136;
    float* Dp = (float*)(xlo + 16 * 136);
    int*   bs = (int*)(Dp + 32 * 132);

    const int tid  = threadIdx.x;
    const int lane = tid & 31;
    const int wid  = tid >> 5;
    const int n0   = blockIdx.x * rpb;
    const int cnt  = max(0, min(rpb, N - n0));

    for (int f = tid; f < cnt * 8; f += 512) {
        int row = f >> 3, q = (f & 7) << 2;
        float4 v = *(const float4*)&g_L[(size_t)(n0 + row) * 32 + q];
        ET[(q + 0) * RP + row] = v.x;
        ET[(q + 1) * RP + row] = v.y;
        ET[(q + 2) * RP + row] = v.z;
        ET[(q + 3) * RP + row] = v.w;
    }
    if (tid < 32) c[tid] = 1.f;
    __syncthreads();

    for (int row = tid; row < cnt; row += 512) {
        float e[32];
        float m = -1e30f;
#pragma unroll
        for (int k = 0; k < 32; k++) { e[k] = ET[k * RP + row]; m = fmaxf(m, e[k]); }
#pragma unroll
        for (int k = 0; k < 32; k++) ET[k * RP + row] = __expf(e[k] - m);
    }
    __syncthreads();

    for (int it = 0; it < ITERS; it++) {
        float cr[32];
#pragma unroll
        for (int k = 0; k < 32; k++) cr[k] = c[k];

        for (int row = tid; row < cnt; row += 512) {
            float s = 0.f;
#pragma unroll
            for (int k = 0; k < 32; k++) s = fmaf(ET[k * RP + row], cr[k], s);
            r[row] = 1.0f / s;
        }
        __syncthreads();

        {
            int cpw = (cnt + 15) >> 4;
            int rs = wid * cpw, re = min(rs + cpw, cnt);
            float tlk = 0.f;
            const float* ETk = &ET[lane * RP];
            for (int row = rs; row < re; row++)
                tlk = fmaf(ETk[row], r[row], tlk);
            red[wid * 33 + lane] = tlk;
        }
        __syncthreads();
        if (tid < 32) {
            float s = 0.f;
#pragma unroll
            for (int w = 0; w < 16; w++) s += red[w * 33 + tid];
            atomicAdd(&g_t[it][tid], s);
        }

        grid_barrier(nb);

        if (tid < 32) c[tid] = NK / __ldcg(&g_t[it][tid]);
        __syncthreads();
    }

    // ---- pooling: out[b] += S^T X via wmma (split bf16) ----
    const int mt = wid & 1;
    const int nt = wid >> 1;
    wmma::fragment<wmma::accumulator, 16, 16, 16, float> pacc;
    wmma::fill_fragment(pacc, 0.f);
    int cur_b = -1;

#define POOL_FLUSH(BB) do { \
    __syncthreads(); \
    wmma::store_matrix_sync(&Dp[(mt * 16) * 132 + nt * 16], pacc, 132, wmma::mem_row_major); \
    __syncthreads(); \
    for (int f2 = tid; f2 < 4096; f2 += 512) { \
        int mm = f2 >> 7, cc2 = f2 & 127; \
        atomicAdd(&out[(((BB) * 32 + mm) << 7) + cc2], Dp[mm * 132 + cc2]); \
    } \
    wmma::fill_fragment(pacc, 0.f); \
} while (0)

    for (int s0 = 0; s0 < cnt; s0 += 16) {
        const int nr = min(16, cnt - s0);
        __syncthreads();
        {
            int row = tid >> 5, q = tid & 31;
            uint2 hi = make_uint2(0u, 0u), lo = make_uint2(0u, 0u);
            if (row < nr) {
                float4 v = ((const float4*)x)[(size_t)(n0 + s0 + row) * 32 + q];
                split4(v.x, v.y, v.z, v.w, hi, lo);
            }
            *(uint2*)&xhi[row * 136 + q * 4] = hi;
            *(uint2*)&xlo[row * 136 + q * 4] = lo;
        }
        {
            int row = tid >> 5, k = tid & 31;
            float sv = 0.f;
            if (row < nr) sv = ET[k * RP + s0 + row] * r[s0 + row] * c[k];
            __nv_bfloat16 h = __float2bfloat16(sv);
            shi[row * 40 + k] = h;
            slo[row * 40 + k] = __float2bfloat16(sv - __bfloat162float(h));
            if (k == 0) bs[row] = (row < nr) ? batch[n0 + s0 + row] : -1;
        }
        __syncthreads();

        int pos = 0;
        while (pos < nr) {
            int seg = bs[pos];
            int e = pos + 1;
            while (e < nr && bs[e] == seg) e++;
            if (seg != cur_b) {
                if (cur_b >= 0) POOL_FLUSH(cur_b);
                cur_b = seg;
            }
            bool full = (pos == 0 && e == nr);
            if (!full) {
                __syncthreads();
                int row = tid >> 5, k = tid & 31;
                float sv = 0.f;
                if (row >= pos && row < e) sv = ET[k * RP + s0 + row] * r[s0 + row] * c[k];
                __nv_bfloat16 h = __float2bfloat16(sv);
                shi[row * 40 + k] = h;
                slo[row * 40 + k] = __float2bfloat16(sv - __bfloat162float(h));
                __syncthreads();
            }
            wmma::fragment<wmma::matrix_a, 16, 16, 16, __nv_bfloat16, wmma::col_major> sa_h, sa_l;
            wmma::fragment<wmma::matrix_b, 16, 16, 16, __nv_bfloat16, wmma::row_major> xb_h, xb_l;
            wmma::load_matrix_sync(sa_h, &shi[mt * 16], 40);
            wmma::load_matrix_sync(sa_l, &slo[mt * 16], 40);
            wmma::load_matrix_sync(xb_h, &xhi[nt * 16], 136);
            wmma::load_matrix_sync(xb_l, &xlo[nt * 16], 136);
            wmma::mma_sync(pacc, sa_h, xb_h, pacc);
            wmma::mma_sync(pacc, sa_h, xb_l, pacc);
            wmma::mma_sync(pacc, sa_l, xb_h, pacc);
            pos = e;
        }
    }
    if (cur_b >= 0) POOL_FLUSH(cur_b);
#undef POOL_FLUSH
}

// ---------------- launch ----------------
extern "C" void kernel_launch(void* const* d_in, const int* in_sizes, int n_in,
                              void* d_out, int out_size)
{
    const float* x       = (const float*)d_in[0];
    const int*   batch   = (const int*)d_in[1];
    const float* W1      = (const float*)d_in[2];
    const float* b1      = (const float*)d_in[3];
    const float* W2      = (const float*)d_in[4];
    const float* b2      = (const float*)d_in[5];
    const float* scaling = (const float*)d_in[6];

    const int N = in_sizes[0] / C_DIM;

    int dev = 0, nsm = 148;
    cudaGetDevice(&dev);
    cudaDeviceGetAttribute(&nsm, cudaDevAttrMultiProcessorCount, dev);

    const int ntiles = (N + 127) >> 7;
    const int gl = ntiles < nsm ? ntiles : nsm;

    // sinkpool config A (1 block/SM) and B (2 blocks/SM)
    const int nbA = nsm;
    const int rpbA = (N + nbA - 1) / nbA;
    const int RPA = rpbA + ((rpbA & 1) ? 2 : 1);
    const size_t smA = ((size_t)32 * RPA + rpbA + 32 + 7056 + 64) * 4;
    const int nbB = nsm * 2;
    const int rpbB = (N + nbB - 1) / nbB;
    const int RPB = rpbB + ((rpbB & 1) ? 2 : 1);
    const size_t smB = ((size_t)32 * RPB + rpbB + 32 + 7056 + 64) * 4;

    cudaFuncSetAttribute(k_logits_tc, cudaFuncAttributeMaxDynamicSharedMemorySize, SMEM_TC);
    cudaFuncSetAttribute(k_sinkpool, cudaFuncAttributeMaxDynamicSharedMemorySize, (int)smA);

    int occ2 = 0;
    cudaOccupancyMaxActiveBlocksPerMultiprocessor(&occ2, k_sinkpool, 512, smB);

    int nb, rpb, RP; size_t sm2;
    if (occ2 >= 2) { nb = nbB; rpb = rpbB; RP = RPB; sm2 = smB; }
    else           { nb = nbA; rpb = rpbA; RP = RPA; sm2 = smA; }

    void* gt_addr = nullptr;
    cudaGetSymbolAddress(&gt_addr, g_t);
    cudaMemsetAsync(gt_addr, 0, sizeof(float) * ITERS * K_DIM);
    cudaMemsetAsync(d_out, 0, (size_t)out_size * sizeof(float));

    k_logits_tc<<<gl, 512, SMEM_TC>>>(x, W1, b1, W2, b2, scaling, N, ntiles);

    const float NK = (float)N / (float)K_DIM + 1e-9f;
    k_sinkpool<<<nb, 512, sm2>>>(x, batch, (float*)d_out, N, rpb, RP, (unsigned)nb, NK);
}